// round 2
// baseline (speedup 1.0000x reference)
#include <cuda_runtime.h>
#include <math.h>

// ---------------------------------------------------------------------------
// BEVFormerLite fused pipeline.
//
// Restructure: out[:,p] = relu( scale * (sampled(W@feats))/denom_p + shift )
//   K1: G[b][cam][pix][o] = sum_c W[o][c] * feats[b][cam][c][pix]   (SGEMM)
//   K2: project BEV points, bilinear-gather G, divide by valid count,
//       fused conv-bias + BN + relu, transposed coalesced store.
// ---------------------------------------------------------------------------

#define NCAM  6
#define CH    256
#define FH    29
#define FW    50
#define NPIX  (FH * FW)          // 1450
#define BEVH  200
#define BEVW  200
#define NP    (BEVH * BEVW)      // 40000
#define NB    4
#define PT    32                 // BEV points per sampling block

// Scratch: G = W @ feats, pixel-major, output-channel contiguous. ~35.6 MB.
__device__ __align__(128) float g_G[NB * NCAM * NPIX * CH];

// ---------------------------------------------------------------------------
// K1: SGEMM  G[slab][pix][o] = sum_c feats[slab][c][pix] * W[o][c]
//   grid: x = pix tiles (12), y = o tiles (2), z = slab (24)
//   block tile 128(pix) x 128(o), K-chunk 16, 256 threads, 8x8 per thread.
// ---------------------------------------------------------------------------
__global__ __launch_bounds__(256) void gemm_G_kernel(
    const float* __restrict__ feats, const float* __restrict__ Wm)
{
    __shared__ float As[16][128];   // [k][pix]
    __shared__ float Bs[16][132];   // [k][o], padded

    const int slab = blockIdx.z;
    const float* A = feats + slab * (CH * NPIX);
    const int pix0 = blockIdx.x * 128;
    const int o0   = blockIdx.y * 128;
    const int tid  = threadIdx.x;

    float acc[8][8];
#pragma unroll
    for (int i = 0; i < 8; i++)
#pragma unroll
        for (int j = 0; j < 8; j++) acc[i][j] = 0.f;

    const int tn = (tid & 15) * 8;   // o offset within tile (fast dim -> coalesced stores)
    const int tm = (tid >> 4) * 8;   // pix offset within tile

    const int mload = tid & 127;     // pix for A loads
    const int kloadA = tid >> 7;     // 0/1
    const int kB = tid & 15;         // k for B loads
    const int nB = tid >> 4;         // o  for B loads

    for (int c0 = 0; c0 < CH; c0 += 16) {
#pragma unroll
        for (int kk = 0; kk < 8; kk++) {
            int k = kloadA + kk * 2;
            int pix = pix0 + mload;
            As[k][mload] = (pix < NPIX) ? A[(c0 + k) * NPIX + pix] : 0.f;
        }
#pragma unroll
        for (int nn = 0; nn < 8; nn++) {
            int n = nB + nn * 16;
            Bs[kB][n] = Wm[(o0 + n) * CH + c0 + kB];
        }
        __syncthreads();

#pragma unroll
        for (int k = 0; k < 16; k++) {
            float4 a0 = *(const float4*)&As[k][tm];
            float4 a1 = *(const float4*)&As[k][tm + 4];
            float4 b0 = *(const float4*)&Bs[k][tn];
            float4 b1 = *(const float4*)&Bs[k][tn + 4];
            float a[8] = {a0.x, a0.y, a0.z, a0.w, a1.x, a1.y, a1.z, a1.w};
            float b[8] = {b0.x, b0.y, b0.z, b0.w, b1.x, b1.y, b1.z, b1.w};
#pragma unroll
            for (int i = 0; i < 8; i++)
#pragma unroll
                for (int j = 0; j < 8; j++)
                    acc[i][j] = fmaf(a[i], b[j], acc[i][j]);
        }
        __syncthreads();
    }

    const int slab_base = slab * (NPIX * CH);
#pragma unroll
    for (int i = 0; i < 8; i++) {
        int pix = pix0 + tm + i;
        if (pix < NPIX) {
            float* dst = &g_G[slab_base + pix * CH + o0 + tn];
            *(float4*)(dst)     = make_float4(acc[i][0], acc[i][1], acc[i][2], acc[i][3]);
            *(float4*)(dst + 4) = make_float4(acc[i][4], acc[i][5], acc[i][6], acc[i][7]);
        }
    }
}

// ---------------------------------------------------------------------------
// K2: projection + bilinear gather of G + epilogue.
//   grid: x = NP/PT point tiles (1250), y = batch (4). 256 threads.
// ---------------------------------------------------------------------------
__global__ __launch_bounds__(256) void sample_kernel(
    const float* __restrict__ K_in,   // [B][N][3][3]
    const float* __restrict__ E_in,   // [B][N][4][4]
    const float* __restrict__ conv_b,
    const float* __restrict__ bn_g,
    const float* __restrict__ bn_b,
    const float* __restrict__ bn_m,
    const float* __restrict__ bn_v,
    float* __restrict__ out)          // [B][256][200][200]
{
    __shared__ float Ri[NCAM][9];
    __shared__ float ti[NCAM][3];
    __shared__ float Km[NCAM][9];
    __shared__ float4 wrec[PT * NCAM];
    __shared__ int4   prec[PT * NCAM];
    __shared__ int    flg[PT * NCAM];
    __shared__ float  dinv[PT];
    __shared__ float  scale_s[CH];
    __shared__ float  shift_s[CH];
    __shared__ float  S[PT * (CH + 1)];   // padded rows -> conflict-free transpose

    const int b   = blockIdx.y;
    const int p0  = blockIdx.x * PT;
    const int tid = threadIdx.x;

    // Fused epilogue constants (per output channel)
    {
        float sc = bn_g[tid] * rsqrtf(bn_v[tid] + 1e-5f);
        scale_s[tid] = sc;
        shift_s[tid] = bn_b[tid] + sc * (conv_b[tid] - bn_m[tid]);
    }

    // Invert extrinsics (cofactor 3x3) + load intrinsics; one thread per cam.
    if (tid < NCAM) {
        const float* E = E_in + (b * NCAM + tid) * 16;
        float r00 = E[0], r01 = E[1], r02 = E[2],  t0 = E[3];
        float r10 = E[4], r11 = E[5], r12 = E[6],  t1 = E[7];
        float r20 = E[8], r21 = E[9], r22 = E[10], t2 = E[11];
        float c00 = r11 * r22 - r12 * r21;
        float c01 = r12 * r20 - r10 * r22;
        float c02 = r10 * r21 - r11 * r20;
        float id = 1.f / (r00 * c00 + r01 * c01 + r02 * c02);
        float i00 = c00 * id;
        float i01 = (r02 * r21 - r01 * r22) * id;
        float i02 = (r01 * r12 - r02 * r11) * id;
        float i10 = c01 * id;
        float i11 = (r00 * r22 - r02 * r20) * id;
        float i12 = (r02 * r10 - r00 * r12) * id;
        float i20 = c02 * id;
        float i21 = (r01 * r20 - r00 * r21) * id;
        float i22 = (r00 * r11 - r01 * r10) * id;
        Ri[tid][0] = i00; Ri[tid][1] = i01; Ri[tid][2] = i02;
        Ri[tid][3] = i10; Ri[tid][4] = i11; Ri[tid][5] = i12;
        Ri[tid][6] = i20; Ri[tid][7] = i21; Ri[tid][8] = i22;
        ti[tid][0] = -(i00 * t0 + i01 * t1 + i02 * t2);
        ti[tid][1] = -(i10 * t0 + i11 * t1 + i12 * t2);
        ti[tid][2] = -(i20 * t0 + i21 * t1 + i22 * t2);
        const float* Kp = K_in + (b * NCAM + tid) * 9;
#pragma unroll
        for (int q = 0; q < 9; q++) Km[tid][q] = Kp[q];
    }
    __syncthreads();

    // Per-(point, cam) projection -> bilinear records.
    if (tid < PT * NCAM) {
        int pt = tid / NCAM, cam = tid % NCAM;
        int p = p0 + pt;
        int ix = p % BEVW, iy = p / BEVW;
        float gx = -49.75f + 0.5f * (float)ix;
        float gy = -49.75f + 0.5f * (float)iy;

        float X = Ri[cam][0] * gx + Ri[cam][1] * gy + ti[cam][0];
        float Y = Ri[cam][3] * gx + Ri[cam][4] * gy + ti[cam][1];
        float Z = Ri[cam][6] * gx + Ri[cam][7] * gy + ti[cam][2];

        float uh = Km[cam][0] * X + Km[cam][1] * Y + Km[cam][2] * Z;
        float vh = Km[cam][3] * X + Km[cam][4] * Y + Km[cam][5] * Z;
        float wh = Km[cam][6] * X + Km[cam][7] * Y + Km[cam][8] * Z;

        float u = uh / (wh + 1e-6f);
        float v = vh / (wh + 1e-6f);
        float uf = u * ((float)FW / 1600.0f);
        float vf = v * ((float)FH / 928.0f);
        float un = uf / (FW - 1.0f) * 2.0f - 1.0f;
        float vn = vf / (FH - 1.0f) * 2.0f - 1.0f;

        bool valid = (Z > 0.1f) && (un >= -1.0f) && (un <= 1.0f)
                                && (vn >= -1.0f) && (vn <= 1.0f);
        if (valid) {
            float xs = (un + 1.0f) * 0.5f * (FW - 1.0f);
            float ys = (vn + 1.0f) * 0.5f * (FH - 1.0f);
            float x0f = floorf(xs), y0f = floorf(ys);
            float wx = xs - x0f, wy = ys - y0f;
            int x0 = (int)x0f, y0 = (int)y0f;
            int x1 = x0 + 1, y1 = y0 + 1;
            float ok00 = (x0 >= 0 && x0 <= FW - 1 && y0 >= 0 && y0 <= FH - 1) ? 1.f : 0.f;
            float ok01 = (x1 >= 0 && x1 <= FW - 1 && y0 >= 0 && y0 <= FH - 1) ? 1.f : 0.f;
            float ok10 = (x0 >= 0 && x0 <= FW - 1 && y1 >= 0 && y1 <= FH - 1) ? 1.f : 0.f;
            float ok11 = (x1 >= 0 && x1 <= FW - 1 && y1 >= 0 && y1 <= FH - 1) ? 1.f : 0.f;
            int xc0 = min(max(x0, 0), FW - 1);
            int xc1 = min(max(x1, 0), FW - 1);
            int yc0 = min(max(y0, 0), FH - 1);
            int yc1 = min(max(y1, 0), FH - 1);
            int base = (b * NCAM + cam) * NPIX;
            prec[tid] = make_int4((base + yc0 * FW + xc0) * CH,
                                  (base + yc0 * FW + xc1) * CH,
                                  (base + yc1 * FW + xc0) * CH,
                                  (base + yc1 * FW + xc1) * CH);
            wrec[tid] = make_float4((1.f - wx) * (1.f - wy) * ok00,
                                    wx * (1.f - wy) * ok01,
                                    (1.f - wx) * wy * ok10,
                                    wx * wy * ok11);
            flg[tid] = 1;
        } else {
            flg[tid] = 0;
        }
    }
    __syncthreads();

    if (tid < PT) {
        int c = 0;
#pragma unroll
        for (int cam = 0; cam < NCAM; cam++) c += flg[tid * NCAM + cam];
        dinv[tid] = 1.0f / ((float)c + 1e-6f);
    }

    // Phase A: thread = output channel; coalesced gathers from G.
    {
        const int o = tid;
        for (int pt = 0; pt < PT; pt++) {
            float acc = 0.f;
#pragma unroll
            for (int cam = 0; cam < NCAM; cam++) {
                int r = pt * NCAM + cam;
                if (flg[r]) {
                    float4 w = wrec[r];
                    int4 pp  = prec[r];
                    acc += w.x * g_G[pp.x + o];
                    acc += w.y * g_G[pp.y + o];
                    acc += w.z * g_G[pp.z + o];
                    acc += w.w * g_G[pp.w + o];
                }
            }
            S[pt * (CH + 1) + o] = acc;
        }
    }
    __syncthreads();

    // Phase B: transpose through smem, coalesced (B,C,H,W) stores + epilogue.
    {
        const int w = tid >> 5;
        const int lane = tid & 31;
        const float di = dinv[lane];
        float* outb = out + (size_t)b * CH * NP + p0 + lane;
#pragma unroll
        for (int r = 0; r < 32; r++) {
            int oo = w + r * 8;
            float val = scale_s[oo] * S[lane * (CH + 1) + oo] * di + shift_s[oo];
            outb[(size_t)oo * NP] = fmaxf(val, 0.f);
        }
    }
}

// ---------------------------------------------------------------------------

extern "C" void kernel_launch(void* const* d_in, const int* in_sizes, int n_in,
                              void* d_out, int out_size)
{
    const float* feats = (const float*)d_in[0];
    const float* K     = (const float*)d_in[1];
    const float* E     = (const float*)d_in[2];
    const float* Wm    = (const float*)d_in[3];
    const float* cb    = (const float*)d_in[4];
    const float* bg    = (const float*)d_in[5];
    const float* bb    = (const float*)d_in[6];
    const float* bm    = (const float*)d_in[7];
    const float* bv    = (const float*)d_in[8];
    float* out = (float*)d_out;

    gemm_G_kernel<<<dim3((NPIX + 127) / 128, CH / 128, NB * NCAM), 256>>>(feats, Wm);
    sample_kernel<<<dim3(NP / PT, NB), 256>>>(K, E, cb, bg, bb, bm, bv, out);
}

// round 3
// speedup vs baseline: 1.0046x; 1.0046x over previous
#include <cuda_runtime.h>
#include <math.h>

// ---------------------------------------------------------------------------
// BEVFormerLite fused pipeline.
//
// Restructure: out[:,p] = relu( scale * (sampled(W@feats))/denom_p + shift )
//   K1: G[b][cam][pix][o] = sum_c W[o][c] * feats[b][cam][c][pix]   (SGEMM)
//   K2: project BEV points, bilinear-gather G, divide by valid count,
//       fused conv-bias + BN + relu, transposed coalesced store.
// ---------------------------------------------------------------------------

#define NCAM  6
#define CH    256
#define FH    29
#define FW    50
#define NPIX  (FH * FW)          // 1450
#define BEVH  200
#define BEVW  200
#define NP    (BEVH * BEVW)      // 40000
#define NB    4
#define PT    32                 // BEV points per sampling block

// Scratch: G = W @ feats, pixel-major, output-channel contiguous. ~35.6 MB.
__device__ __align__(128) float g_G[NB * NCAM * NPIX * CH];

// ---------------------------------------------------------------------------
// K1: SGEMM  G[slab][pix][o] = sum_c feats[slab][c][pix] * W[o][c]
//   grid: x = pix tiles (12), y = o tiles (2), z = slab (24)
//   block tile 128(pix) x 128(o), K-chunk 16, 256 threads, 8x8 per thread.
// ---------------------------------------------------------------------------
__global__ __launch_bounds__(256) void gemm_G_kernel(
    const float* __restrict__ feats, const float* __restrict__ Wm)
{
    __shared__ float As[16][128];   // [k][pix]
    __shared__ float Bs[16][132];   // [k][o], padded

    const int slab = blockIdx.z;
    const float* A = feats + slab * (CH * NPIX);
    const int pix0 = blockIdx.x * 128;
    const int o0   = blockIdx.y * 128;
    const int tid  = threadIdx.x;

    float acc[8][8];
#pragma unroll
    for (int i = 0; i < 8; i++)
#pragma unroll
        for (int j = 0; j < 8; j++) acc[i][j] = 0.f;

    const int tn = (tid & 15) * 8;   // o offset within tile (fast dim -> coalesced stores)
    const int tm = (tid >> 4) * 8;   // pix offset within tile

    const int mload = tid & 127;     // pix for A loads
    const int kloadA = tid >> 7;     // 0/1
    const int kB = tid & 15;         // k for B loads
    const int nB = tid >> 4;         // o  for B loads

    for (int c0 = 0; c0 < CH; c0 += 16) {
#pragma unroll
        for (int kk = 0; kk < 8; kk++) {
            int k = kloadA + kk * 2;
            int pix = pix0 + mload;
            As[k][mload] = (pix < NPIX) ? A[(c0 + k) * NPIX + pix] : 0.f;
        }
#pragma unroll
        for (int nn = 0; nn < 8; nn++) {
            int n = nB + nn * 16;
            Bs[kB][n] = Wm[(o0 + n) * CH + c0 + kB];
        }
        __syncthreads();

#pragma unroll
        for (int k = 0; k < 16; k++) {
            float4 a0 = *(const float4*)&As[k][tm];
            float4 a1 = *(const float4*)&As[k][tm + 4];
            float4 b0 = *(const float4*)&Bs[k][tn];
            float4 b1 = *(const float4*)&Bs[k][tn + 4];
            float a[8] = {a0.x, a0.y, a0.z, a0.w, a1.x, a1.y, a1.z, a1.w};
            float b[8] = {b0.x, b0.y, b0.z, b0.w, b1.x, b1.y, b1.z, b1.w};
#pragma unroll
            for (int i = 0; i < 8; i++)
#pragma unroll
                for (int j = 0; j < 8; j++)
                    acc[i][j] = fmaf(a[i], b[j], acc[i][j]);
        }
        __syncthreads();
    }

    const int slab_base = slab * (NPIX * CH);
#pragma unroll
    for (int i = 0; i < 8; i++) {
        int pix = pix0 + tm + i;
        if (pix < NPIX) {
            float* dst = &g_G[slab_base + pix * CH + o0 + tn];
            *(float4*)(dst)     = make_float4(acc[i][0], acc[i][1], acc[i][2], acc[i][3]);
            *(float4*)(dst + 4) = make_float4(acc[i][4], acc[i][5], acc[i][6], acc[i][7]);
        }
    }
}

// ---------------------------------------------------------------------------
// K2: projection + bilinear gather of G + epilogue.
//   grid: x = NP/PT point tiles (1250), y = batch (4). 256 threads.
// ---------------------------------------------------------------------------
__global__ __launch_bounds__(256) void sample_kernel(
    const float* __restrict__ K_in,   // [B][N][3][3]
    const float* __restrict__ E_in,   // [B][N][4][4]
    const float* __restrict__ conv_b,
    const float* __restrict__ bn_g,
    const float* __restrict__ bn_b,
    const float* __restrict__ bn_m,
    const float* __restrict__ bn_v,
    float* __restrict__ out)          // [B][256][200][200]
{
    __shared__ float Ri[NCAM][9];
    __shared__ float ti[NCAM][3];
    __shared__ float Km[NCAM][9];
    __shared__ float4 wrec[PT * NCAM];
    __shared__ int4   prec[PT * NCAM];
    __shared__ int    flg[PT * NCAM];
    __shared__ float  dinv[PT];
    __shared__ float  scale_s[CH];
    __shared__ float  shift_s[CH];
    __shared__ float  S[PT * (CH + 1)];   // padded rows -> conflict-free transpose

    const int b   = blockIdx.y;
    const int p0  = blockIdx.x * PT;
    const int tid = threadIdx.x;

    // Fused epilogue constants (per output channel)
    {
        float sc = bn_g[tid] * rsqrtf(bn_v[tid] + 1e-5f);
        scale_s[tid] = sc;
        shift_s[tid] = bn_b[tid] + sc * (conv_b[tid] - bn_m[tid]);
    }

    // Invert extrinsics (cofactor 3x3) + load intrinsics; one thread per cam.
    if (tid < NCAM) {
        const float* E = E_in + (b * NCAM + tid) * 16;
        float r00 = E[0], r01 = E[1], r02 = E[2],  t0 = E[3];
        float r10 = E[4], r11 = E[5], r12 = E[6],  t1 = E[7];
        float r20 = E[8], r21 = E[9], r22 = E[10], t2 = E[11];
        float c00 = r11 * r22 - r12 * r21;
        float c01 = r12 * r20 - r10 * r22;
        float c02 = r10 * r21 - r11 * r20;
        float id = 1.f / (r00 * c00 + r01 * c01 + r02 * c02);
        float i00 = c00 * id;
        float i01 = (r02 * r21 - r01 * r22) * id;
        float i02 = (r01 * r12 - r02 * r11) * id;
        float i10 = c01 * id;
        float i11 = (r00 * r22 - r02 * r20) * id;
        float i12 = (r02 * r10 - r00 * r12) * id;
        float i20 = c02 * id;
        float i21 = (r01 * r20 - r00 * r21) * id;
        float i22 = (r00 * r11 - r01 * r10) * id;
        Ri[tid][0] = i00; Ri[tid][1] = i01; Ri[tid][2] = i02;
        Ri[tid][3] = i10; Ri[tid][4] = i11; Ri[tid][5] = i12;
        Ri[tid][6] = i20; Ri[tid][7] = i21; Ri[tid][8] = i22;
        ti[tid][0] = -(i00 * t0 + i01 * t1 + i02 * t2);
        ti[tid][1] = -(i10 * t0 + i11 * t1 + i12 * t2);
        ti[tid][2] = -(i20 * t0 + i21 * t1 + i22 * t2);
        const float* Kp = K_in + (b * NCAM + tid) * 9;
#pragma unroll
        for (int q = 0; q < 9; q++) Km[tid][q] = Kp[q];
    }
    __syncthreads();

    // Per-(point, cam) projection -> bilinear records.
    if (tid < PT * NCAM) {
        int pt = tid / NCAM, cam = tid % NCAM;
        int p = p0 + pt;
        int ix = p % BEVW, iy = p / BEVW;
        float gx = -49.75f + 0.5f * (float)ix;
        float gy = -49.75f + 0.5f * (float)iy;

        float X = Ri[cam][0] * gx + Ri[cam][1] * gy + ti[cam][0];
        float Y = Ri[cam][3] * gx + Ri[cam][4] * gy + ti[cam][1];
        float Z = Ri[cam][6] * gx + Ri[cam][7] * gy + ti[cam][2];

        float uh = Km[cam][0] * X + Km[cam][1] * Y + Km[cam][2] * Z;
        float vh = Km[cam][3] * X + Km[cam][4] * Y + Km[cam][5] * Z;
        float wh = Km[cam][6] * X + Km[cam][7] * Y + Km[cam][8] * Z;

        float u = uh / (wh + 1e-6f);
        float v = vh / (wh + 1e-6f);
        float uf = u * ((float)FW / 1600.0f);
        float vf = v * ((float)FH / 928.0f);
        float un = uf / (FW - 1.0f) * 2.0f - 1.0f;
        float vn = vf / (FH - 1.0f) * 2.0f - 1.0f;

        bool valid = (Z > 0.1f) && (un >= -1.0f) && (un <= 1.0f)
                                && (vn >= -1.0f) && (vn <= 1.0f);
        if (valid) {
            float xs = (un + 1.0f) * 0.5f * (FW - 1.0f);
            float ys = (vn + 1.0f) * 0.5f * (FH - 1.0f);
            float x0f = floorf(xs), y0f = floorf(ys);
            float wx = xs - x0f, wy = ys - y0f;
            int x0 = (int)x0f, y0 = (int)y0f;
            int x1 = x0 + 1, y1 = y0 + 1;
            float ok00 = (x0 >= 0 && x0 <= FW - 1 && y0 >= 0 && y0 <= FH - 1) ? 1.f : 0.f;
            float ok01 = (x1 >= 0 && x1 <= FW - 1 && y0 >= 0 && y0 <= FH - 1) ? 1.f : 0.f;
            float ok10 = (x0 >= 0 && x0 <= FW - 1 && y1 >= 0 && y1 <= FH - 1) ? 1.f : 0.f;
            float ok11 = (x1 >= 0 && x1 <= FW - 1 && y1 >= 0 && y1 <= FH - 1) ? 1.f : 0.f;
            int xc0 = min(max(x0, 0), FW - 1);
            int xc1 = min(max(x1, 0), FW - 1);
            int yc0 = min(max(y0, 0), FH - 1);
            int yc1 = min(max(y1, 0), FH - 1);
            int base = (b * NCAM + cam) * NPIX;
            prec[tid] = make_int4((base + yc0 * FW + xc0) * CH,
                                  (base + yc0 * FW + xc1) * CH,
                                  (base + yc1 * FW + xc0) * CH,
                                  (base + yc1 * FW + xc1) * CH);
            wrec[tid] = make_float4((1.f - wx) * (1.f - wy) * ok00,
                                    wx * (1.f - wy) * ok01,
                                    (1.f - wx) * wy * ok10,
                                    wx * wy * ok11);
            flg[tid] = 1;
        } else {
            flg[tid] = 0;
        }
    }
    __syncthreads();

    if (tid < PT) {
        int c = 0;
#pragma unroll
        for (int cam = 0; cam < NCAM; cam++) c += flg[tid * NCAM + cam];
        dinv[tid] = 1.0f / ((float)c + 1e-6f);
    }

    // Phase A: thread = output channel; coalesced gathers from G.
    {
        const int o = tid;
        for (int pt = 0; pt < PT; pt++) {
            float acc = 0.f;
#pragma unroll
            for (int cam = 0; cam < NCAM; cam++) {
                int r = pt * NCAM + cam;
                if (flg[r]) {
                    float4 w = wrec[r];
                    int4 pp  = prec[r];
                    acc += w.x * g_G[pp.x + o];
                    acc += w.y * g_G[pp.y + o];
                    acc += w.z * g_G[pp.z + o];
                    acc += w.w * g_G[pp.w + o];
                }
            }
            S[pt * (CH + 1) + o] = acc;
        }
    }
    __syncthreads();

    // Phase B: transpose through smem, coalesced (B,C,H,W) stores + epilogue.
    {
        const int w = tid >> 5;
        const int lane = tid & 31;
        const float di = dinv[lane];
        float* outb = out + (size_t)b * CH * NP + p0 + lane;
#pragma unroll
        for (int r = 0; r < 32; r++) {
            int oo = w + r * 8;
            float val = scale_s[oo] * S[lane * (CH + 1) + oo] * di + shift_s[oo];
            outb[(size_t)oo * NP] = fmaxf(val, 0.f);
        }
    }
}

// ---------------------------------------------------------------------------

extern "C" void kernel_launch(void* const* d_in, const int* in_sizes, int n_in,
                              void* d_out, int out_size)
{
    const float* feats = (const float*)d_in[0];
    const float* K     = (const float*)d_in[1];
    const float* E     = (const float*)d_in[2];
    const float* Wm    = (const float*)d_in[3];
    const float* cb    = (const float*)d_in[4];
    const float* bg    = (const float*)d_in[5];
    const float* bb    = (const float*)d_in[6];
    const float* bm    = (const float*)d_in[7];
    const float* bv    = (const float*)d_in[8];
    float* out = (float*)d_out;

    gemm_G_kernel<<<dim3((NPIX + 127) / 128, CH / 128, NB * NCAM), 256>>>(feats, Wm);
    sample_kernel<<<dim3(NP / PT, NB), 256>>>(K, E, cb, bg, bb, bm, bv, out);
}